// round 16
// baseline (speedup 1.0000x reference)
#include <cuda_runtime.h>

// CosineSim3D — single fully-fused kernel (per batch):
//   phase B: s_b = sum of normalized b rows   (ldcs, 2-row interleaved chains)
//   phase A: score a rows vs s_b              (ldcs, 2-row interleave)
//   softmax over 1024 scores
//   broadcast write out (plain write-back stores -> L2-resident)
//
// a, b : [128, 1024, 300] fp32   out : [128, 1024, 300] fp32

#define BATCH   128
#define NROWS   1024
#define DIM     300
#define NF4     75
#define EPSV    1e-7f

__device__ __forceinline__ float dot4(float4 x, float4 y) {
    return x.x * y.x + x.y * y.y + x.z * y.z + x.w * y.w;
}
__device__ __forceinline__ void fma4(float4& a, float4 v, float s) {
    a.x += v.x * s; a.y += v.y * s; a.z += v.z * s; a.w += v.w * s;
}
__device__ __forceinline__ void add4(float4& a, float4 v) {
    a.x += v.x; a.y += v.y; a.z += v.z; a.w += v.w;
}

// ---------------------------------------------------------------------------
// grid = 128 (batch), block = 1024 (32 warps)
// ---------------------------------------------------------------------------
__global__ __launch_bounds__(1024, 1) void fused_all_kernel(
    const float* __restrict__ a, const float* __restrict__ b,
    float* __restrict__ out)
{
    const int batch = blockIdx.x;
    const int warp  = threadIdx.x >> 5;
    const int lane  = threadIdx.x & 31;

    __shared__ float4 sw4[32][NF4 + 1];   // 38.9 KB cross-warp partials
    __shared__ float4 ssh4[NF4];          // s_b
    __shared__ float  probs[NROWS];
    __shared__ float  red[32];

    const float4 z4 = make_float4(0.f, 0.f, 0.f, 0.f);

    // ---- phase B: s_b = sum of normalized b rows (2-row dual chains) -----
    {
        const float4* b4 = reinterpret_cast<const float4*>(b)
                         + (size_t)batch * NROWS * NF4;
        float4 acc0 = z4, acc1 = z4, acc2 = z4;

        // rows rA = warp + 64i, rB = rA + 32  (i = 0..15)
#pragma unroll 2
        for (int i = 0; i < 16; i++) {
            const int rA = warp + 64 * i;
            const float4* rowA = b4 + rA * NF4;
            const float4* rowB = rowA + 32 * NF4;
            const float4 A0 = __ldcs(rowA + lane);
            const float4 A1 = __ldcs(rowA + lane + 32);
            const float4 B0 = __ldcs(rowB + lane);
            const float4 B1 = __ldcs(rowB + lane + 32);
            const float4 A2 = (lane < NF4 - 64) ? __ldcs(rowA + lane + 64) : z4;
            const float4 B2 = (lane < NF4 - 64) ? __ldcs(rowB + lane + 64) : z4;

            float sA = dot4(A0, A0) + dot4(A1, A1) + dot4(A2, A2);
            float sB = dot4(B0, B0) + dot4(B1, B1) + dot4(B2, B2);
#pragma unroll
            for (int o = 16; o > 0; o >>= 1) {
                sA += __shfl_xor_sync(0xffffffffu, sA, o);
                sB += __shfl_xor_sync(0xffffffffu, sB, o);
            }
            const float iA = rsqrtf(fmaxf(sA, EPSV));
            const float iB = rsqrtf(fmaxf(sB, EPSV));
            fma4(acc0, A0, iA); fma4(acc0, B0, iB);
            fma4(acc1, A1, iA); fma4(acc1, B1, iB);
            fma4(acc2, A2, iA); fma4(acc2, B2, iB);
        }
        sw4[warp][lane]      = acc0;
        sw4[warp][lane + 32] = acc1;
        if (lane < NF4 - 64) sw4[warp][lane + 64] = acc2;
    }
    __syncthreads();

    // fold 32 warp-partials -> ssh4 (75 active threads, fixed order)
    if (threadIdx.x < NF4) {
        float4 t = sw4[0][threadIdx.x];
#pragma unroll
        for (int w = 1; w < 32; w++) add4(t, sw4[w][threadIdx.x]);
        ssh4[threadIdx.x] = t;
    }
    __syncthreads();

    // ---- phase A: scores of a rows (2-row interleave) --------------------
    {
        const float4 s0 = ssh4[lane];
        const float4 s1 = ssh4[lane + 32];
        const float4 s2 = (lane < NF4 - 64) ? ssh4[lane + 64] : z4;

        const float4* a4 = reinterpret_cast<const float4*>(a)
                         + (size_t)batch * NROWS * NF4;

#pragma unroll 2
        for (int i = 0; i < 16; i++) {
            const int rA = warp + 64 * i;
            const float4* rowA = a4 + rA * NF4;
            const float4* rowB = rowA + 32 * NF4;
            const float4 A0 = __ldcs(rowA + lane);
            const float4 A1 = __ldcs(rowA + lane + 32);
            const float4 B0 = __ldcs(rowB + lane);
            const float4 B1 = __ldcs(rowB + lane + 32);
            const float4 A2 = (lane < NF4 - 64) ? __ldcs(rowA + lane + 64) : z4;
            const float4 B2 = (lane < NF4 - 64) ? __ldcs(rowB + lane + 64) : z4;

            float dA = dot4(A0, s0) + dot4(A1, s1) + dot4(A2, s2);
            float nA = dot4(A0, A0) + dot4(A1, A1) + dot4(A2, A2);
            float dB = dot4(B0, s0) + dot4(B1, s1) + dot4(B2, s2);
            float nB = dot4(B0, B0) + dot4(B1, B1) + dot4(B2, B2);
#pragma unroll
            for (int o = 16; o > 0; o >>= 1) {
                dA += __shfl_xor_sync(0xffffffffu, dA, o);
                nA += __shfl_xor_sync(0xffffffffu, nA, o);
                dB += __shfl_xor_sync(0xffffffffu, dB, o);
                nB += __shfl_xor_sync(0xffffffffu, nB, o);
            }
            if (lane == 0) {
                probs[rA]      = dA * rsqrtf(fmaxf(nA, EPSV));
                probs[rA + 32] = dB * rsqrtf(fmaxf(nB, EPSV));
            }
        }
    }
    __syncthreads();

    // ---- softmax over 1024 scores (thread t owns element t) --------------
    const float x = probs[threadIdx.x];

    float m = x;
#pragma unroll
    for (int o = 16; o > 0; o >>= 1)
        m = fmaxf(m, __shfl_xor_sync(0xffffffffu, m, o));
    if (lane == 0) red[warp] = m;
    __syncthreads();
    if (warp == 0) {
        float t = red[lane];
#pragma unroll
        for (int o = 16; o > 0; o >>= 1)
            t = fmaxf(t, __shfl_xor_sync(0xffffffffu, t, o));
        if (lane == 0) red[0] = t;
    }
    __syncthreads();
    const float M = red[0];

    const float e = __expf(x - M);

    float sum = e;
#pragma unroll
    for (int o = 16; o > 0; o >>= 1)
        sum += __shfl_xor_sync(0xffffffffu, sum, o);
    __syncthreads();                  // red[] reuse barrier
    if (lane == 0) red[warp] = sum;
    __syncthreads();
    if (warp == 0) {
        float t = red[lane];
#pragma unroll
        for (int o = 16; o > 0; o >>= 1)
            t += __shfl_xor_sync(0xffffffffu, t, o);
        if (lane == 0) red[0] = t;
    }
    __syncthreads();

    probs[threadIdx.x] = e * __frcp_rn(red[0]);
    __syncthreads();

    // ---- broadcast write: warp-per-row, plain write-back stores ----------
    float4* o4 = reinterpret_cast<float4*>(out) + (size_t)batch * NROWS * NF4;
#pragma unroll 4
    for (int r = warp; r < NROWS; r += 32) {
        const float p = probs[r];
        const float4 pv = make_float4(p, p, p, p);
        float4* row = o4 + r * NF4;
        row[lane]      = pv;
        row[lane + 32] = pv;
        if (lane < NF4 - 64) row[lane + 64] = pv;
    }
}

// ---------------------------------------------------------------------------
extern "C" void kernel_launch(void* const* d_in, const int* in_sizes, int n_in,
                              void* d_out, int out_size)
{
    const float* a = (const float*)d_in[0];
    const float* b = (const float*)d_in[1];
    float* out = (float*)d_out;

    fused_all_kernel<<<BATCH, 1024>>>(a, b, out);
}